// round 1
// baseline (speedup 1.0000x reference)
#include <cuda_runtime.h>
#include <math.h>

// Problem constants
#define BB   16
#define CC   512
#define CBOT 64
#define NN   4096   // 64*64
#define NSPLIT 8    // split-K blocks for logits

// ---------------------------------------------------------------------------
// Scratch (static __device__ arrays — no runtime allocation)
// ---------------------------------------------------------------------------
__device__ float g_q[BB * CBOT * NN];          // 16 MB
__device__ float g_k[BB * CBOT * NN];          // 16 MB
__device__ float g_v[BB * CBOT * NN];          // 16 MB
__device__ float g_lp[BB * NSPLIT * CBOT * CBOT]; // partial logits, 2 MB
__device__ float g_M[BB * CC * CBOT];          // gamma * (w_o @ attn), 2 MB

// ---------------------------------------------------------------------------
// Kernel 1: QKV projection.
// grid (NN/128, 3, B), block 256.  Output tile [64 rows, 128 cols], BK=32.
// Each thread computes a 4x8 microtile.
// ---------------------------------------------------------------------------
__global__ __launch_bounds__(256) void qkv_kernel(
    const float* __restrict__ x,
    const float* __restrict__ wq, const float* __restrict__ bq,
    const float* __restrict__ wk, const float* __restrict__ bk,
    const float* __restrict__ wv, const float* __restrict__ bv)
{
    __shared__ float Ws[32][65];    // [k][m], padded (odd) -> conflict-free
    __shared__ float Xs[32][128];   // [k][n], float4-friendly

    const int b     = blockIdx.z;
    const int which = blockIdx.y;
    const float* W    = (which == 0) ? wq : ((which == 1) ? wk : wv);
    const float* bias = (which == 0) ? bq : ((which == 1) ? bk : bv);
    float* outbase    = (which == 0) ? g_q : ((which == 1) ? g_k : g_v);
    float* out        = outbase + (size_t)b * CBOT * NN;
    const float* xb   = x + (size_t)b * CC * NN;

    const int n_base = blockIdx.x * 128;
    const int tid = threadIdx.x;
    const int ty = tid >> 4, tx = tid & 15;
    const int m0 = ty * 4, n0 = tx * 8;

    float acc[4][8];
    #pragma unroll
    for (int i = 0; i < 4; i++)
        #pragma unroll
        for (int j = 0; j < 8; j++) acc[i][j] = 0.f;

    for (int k0 = 0; k0 < CC; k0 += 32) {
        // Load W chunk [64, 32] -> Ws[k][m]
        #pragma unroll
        for (int i = 0; i < 8; i++) {
            int idx = tid * 8 + i;        // 0..2047
            int m = idx >> 5, k = idx & 31;
            Ws[k][m] = W[m * CC + k0 + k];
        }
        // Load x chunk [32, 128] -> Xs[k][n]  (float4)
        const float4* xsrc = reinterpret_cast<const float4*>(xb + (size_t)k0 * NN + n_base);
        #pragma unroll
        for (int j = 0; j < 4; j++) {
            int idx4 = tid + j * 256;     // 0..1023
            int k = idx4 >> 5, n4 = idx4 & 31;
            *reinterpret_cast<float4*>(&Xs[k][n4 * 4]) = xsrc[(size_t)k * (NN / 4) + n4];
        }
        __syncthreads();

        #pragma unroll
        for (int k = 0; k < 32; k++) {
            float a[4];
            #pragma unroll
            for (int i = 0; i < 4; i++) a[i] = Ws[k][m0 + i];
            float4 v0 = *reinterpret_cast<const float4*>(&Xs[k][n0]);
            float4 v1 = *reinterpret_cast<const float4*>(&Xs[k][n0 + 4]);
            float xv[8] = {v0.x, v0.y, v0.z, v0.w, v1.x, v1.y, v1.z, v1.w};
            #pragma unroll
            for (int i = 0; i < 4; i++)
                #pragma unroll
                for (int j = 0; j < 8; j++)
                    acc[i][j] = fmaf(a[i], xv[j], acc[i][j]);
        }
        __syncthreads();
    }

    // Epilogue: add bias, float4 stores
    #pragma unroll
    for (int i = 0; i < 4; i++) {
        float bi = bias[m0 + i];
        float4 r0 = {acc[i][0] + bi, acc[i][1] + bi, acc[i][2] + bi, acc[i][3] + bi};
        float4 r1 = {acc[i][4] + bi, acc[i][5] + bi, acc[i][6] + bi, acc[i][7] + bi};
        float* orow = out + (size_t)(m0 + i) * NN + n_base + n0;
        *reinterpret_cast<float4*>(orow)     = r0;
        *reinterpret_cast<float4*>(orow + 4) = r1;
    }
}

// ---------------------------------------------------------------------------
// Kernel 2: split-K logits.  logits[b,c,d] = sum_n q[b,c,n]*k[b,d,n]
// grid (NSPLIT, B), block 256.  Each block covers 512 n-columns, writes
// its own [64,64] partial.  Thread microtile 4x4.
// ---------------------------------------------------------------------------
__global__ __launch_bounds__(256) void logits_kernel()
{
    __shared__ float Qs[32][65];   // [n][c]
    __shared__ float Ks[32][65];   // [n][d]

    const int s = blockIdx.x, b = blockIdx.y;
    const int tid = threadIdx.x;
    const int ty = tid >> 4, tx = tid & 15;
    const int c0 = ty * 4, d0 = tx * 4;

    const float* qb = g_q + (size_t)b * CBOT * NN + s * (NN / NSPLIT);
    const float* kb = g_k + (size_t)b * CBOT * NN + s * (NN / NSPLIT);

    float acc[4][4];
    #pragma unroll
    for (int i = 0; i < 4; i++)
        #pragma unroll
        for (int j = 0; j < 4; j++) acc[i][j] = 0.f;

    for (int n0 = 0; n0 < (NN / NSPLIT); n0 += 32) {
        #pragma unroll
        for (int i = 0; i < 8; i++) {
            int idx = tid * 8 + i;
            int c = idx >> 5, nn = idx & 31;
            Qs[nn][c] = qb[(size_t)c * NN + n0 + nn];
            Ks[nn][c] = kb[(size_t)c * NN + n0 + nn];
        }
        __syncthreads();
        #pragma unroll
        for (int nn = 0; nn < 32; nn++) {
            float a[4], e[4];
            #pragma unroll
            for (int i = 0; i < 4; i++) a[i] = Qs[nn][c0 + i];
            #pragma unroll
            for (int j = 0; j < 4; j++) e[j] = Ks[nn][d0 + j];
            #pragma unroll
            for (int i = 0; i < 4; i++)
                #pragma unroll
                for (int j = 0; j < 4; j++)
                    acc[i][j] = fmaf(a[i], e[j], acc[i][j]);
        }
        __syncthreads();
    }

    float* lp = g_lp + (size_t)(b * NSPLIT + s) * CBOT * CBOT;
    #pragma unroll
    for (int i = 0; i < 4; i++)
        #pragma unroll
        for (int j = 0; j < 4; j++)
            lp[(c0 + i) * CBOT + d0 + j] = acc[i][j];
}

// ---------------------------------------------------------------------------
// Kernel 3: reduce partials -> softmax(rows) -> M = gamma * (w_o @ attn).
// grid (B, 4), block 256.  Each block redundantly does the (tiny) softmax,
// then computes 128 rows of M.
// ---------------------------------------------------------------------------
__global__ __launch_bounds__(256) void softmax_m_kernel(
    const float* __restrict__ w_o, const float* __restrict__ gamma)
{
    __shared__ float L[CBOT * CBOT];  // 16 KB
    const int b = blockIdx.x;
    const int cbase = blockIdx.y * 128;
    const int tid = threadIdx.x;

    // Reduce NSPLIT partials
    #pragma unroll
    for (int t = 0; t < 16; t++) {
        int idx = tid + 256 * t;
        float s0 = 0.f;
        #pragma unroll
        for (int s = 0; s < NSPLIT; s++)
            s0 += g_lp[(size_t)(b * NSPLIT + s) * (CBOT * CBOT) + idx];
        L[idx] = s0;
    }
    __syncthreads();

    // Row softmax (64 rows, threads 0..63)
    if (tid < CBOT) {
        float* row = &L[tid * CBOT];
        float mx = row[0];
        #pragma unroll
        for (int d = 1; d < CBOT; d++) mx = fmaxf(mx, row[d]);
        float sum = 0.f;
        #pragma unroll
        for (int d = 0; d < CBOT; d++) { float e = expf(row[d] - mx); row[d] = e; sum += e; }
        float inv = 1.f / sum;
        #pragma unroll
        for (int d = 0; d < CBOT; d++) row[d] *= inv;
    }
    __syncthreads();

    // M[c][d] = gamma * sum_e w_o[c][e] * attn[e][d]   (128 c-rows per block)
    const float g = gamma[0];
    for (int o = tid; o < 128 * CBOT; o += 256) {
        int c = cbase + (o >> 6);
        int d = o & 63;
        float sum = 0.f;
        #pragma unroll
        for (int e = 0; e < CBOT; e++)
            sum = fmaf(w_o[c * CBOT + e], L[e * CBOT + d], sum);
        g_M[((size_t)b * CC + c) * CBOT + d] = g * sum;
    }
}

// ---------------------------------------------------------------------------
// Kernel 4: out = M @ v + gamma*b_o + x.
// grid (NN/128, CC/128, B), block 256.  Tile [128 c, 128 n], K=64 in two
// 32-chunks.  Thread microtile 8x8.
// ---------------------------------------------------------------------------
__global__ __launch_bounds__(256) void out_kernel(
    const float* __restrict__ x,
    const float* __restrict__ b_o, const float* __restrict__ gamma,
    float* __restrict__ out)
{
    __shared__ float Ms[32][129];   // [k][c], odd pad
    __shared__ float Vs[32][128];   // [k][n]

    const int b = blockIdx.z;
    const int c_base = blockIdx.y * 128;
    const int n_base = blockIdx.x * 128;
    const int tid = threadIdx.x;
    const int ty = tid >> 4, tx = tid & 15;
    const int ci0 = ty * 8, n0 = tx * 8;

    const float* Mb = g_M + ((size_t)b * CC + c_base) * CBOT;
    const float* vb = g_v + (size_t)b * CBOT * NN;

    float acc[8][8];
    #pragma unroll
    for (int i = 0; i < 8; i++)
        #pragma unroll
        for (int j = 0; j < 8; j++) acc[i][j] = 0.f;

    for (int k0 = 0; k0 < CBOT; k0 += 32) {
        // M tile [128 c, 32 k] -> Ms[k][c]
        #pragma unroll
        for (int i = 0; i < 16; i++) {
            int idx = tid * 16 + i;        // 0..4095
            int c = idx >> 5, k = idx & 31;
            Ms[k][c] = Mb[(size_t)c * CBOT + k0 + k];
        }
        // v tile [32 k, 128 n] -> Vs[k][n] (float4)
        const float4* vsrc = reinterpret_cast<const float4*>(vb + (size_t)k0 * NN + n_base);
        #pragma unroll
        for (int j = 0; j < 4; j++) {
            int idx4 = tid + j * 256;
            int k = idx4 >> 5, n4 = idx4 & 31;
            *reinterpret_cast<float4*>(&Vs[k][n4 * 4]) = vsrc[(size_t)k * (NN / 4) + n4];
        }
        __syncthreads();

        #pragma unroll
        for (int k = 0; k < 32; k++) {
            float a[8];
            #pragma unroll
            for (int i = 0; i < 8; i++) a[i] = Ms[k][ci0 + i];
            float4 v0 = *reinterpret_cast<const float4*>(&Vs[k][n0]);
            float4 v1 = *reinterpret_cast<const float4*>(&Vs[k][n0 + 4]);
            float xv[8] = {v0.x, v0.y, v0.z, v0.w, v1.x, v1.y, v1.z, v1.w};
            #pragma unroll
            for (int i = 0; i < 8; i++)
                #pragma unroll
                for (int j = 0; j < 8; j++)
                    acc[i][j] = fmaf(a[i], xv[j], acc[i][j]);
        }
        __syncthreads();
    }

    // Epilogue: += gamma*b_o + residual x, float4 stores
    const float g = gamma[0];
    #pragma unroll
    for (int i = 0; i < 8; i++) {
        int c = c_base + ci0 + i;
        float gb = g * b_o[c];
        const float* xr = x + ((size_t)b * CC + c) * NN + n_base + n0;
        float* orow = out + ((size_t)b * CC + c) * NN + n_base + n0;
        float4 x0 = *reinterpret_cast<const float4*>(xr);
        float4 x1 = *reinterpret_cast<const float4*>(xr + 4);
        float4 r0 = {acc[i][0] + gb + x0.x, acc[i][1] + gb + x0.y,
                     acc[i][2] + gb + x0.z, acc[i][3] + gb + x0.w};
        float4 r1 = {acc[i][4] + gb + x1.x, acc[i][5] + gb + x1.y,
                     acc[i][6] + gb + x1.z, acc[i][7] + gb + x1.w};
        *reinterpret_cast<float4*>(orow)     = r0;
        *reinterpret_cast<float4*>(orow + 4) = r1;
    }
}

// ---------------------------------------------------------------------------
// Launch
// ---------------------------------------------------------------------------
extern "C" void kernel_launch(void* const* d_in, const int* in_sizes, int n_in,
                              void* d_out, int out_size)
{
    const float* x     = (const float*)d_in[0];
    const float* w_q   = (const float*)d_in[1];
    const float* b_q   = (const float*)d_in[2];
    const float* w_k   = (const float*)d_in[3];
    const float* b_k   = (const float*)d_in[4];
    const float* w_v   = (const float*)d_in[5];
    const float* b_v   = (const float*)d_in[6];
    const float* w_o   = (const float*)d_in[7];
    const float* b_o   = (const float*)d_in[8];
    const float* gamma = (const float*)d_in[9];
    float* out = (float*)d_out;

    qkv_kernel<<<dim3(NN / 128, 3, BB), 256>>>(x, w_q, b_q, w_k, b_k, w_v, b_v);
    logits_kernel<<<dim3(NSPLIT, BB), 256>>>();
    softmax_m_kernel<<<dim3(BB, 4), 256>>>(w_o, gamma);
    out_kernel<<<dim3(NN / 128, CC / 128, BB), 256>>>(x, b_o, gamma, out);
}